// round 16
// baseline (speedup 1.0000x reference)
#include <cuda_runtime.h>
#include <cuda_fp16.h>
#include <cstdint>

#define MAXN 131072
#define EPB 512   // edges per block (256 threads x 2)

// Packed tables: one uint4 (16B) per node per table.
// 12-bit unsigned q values (bias 2048) + fp16 row scale.
__device__ uint4 g_Y[MAXN];
__device__ uint4 g_Z[MAXN];

// ---------------- helpers ----------------
__device__ __forceinline__ unsigned long long packf2(float lo, float hi) {
    unsigned long long r;
    asm("mov.b64 %0, {%1, %2};" : "=l"(r) : "f"(lo), "f"(hi));
    return r;
}
__device__ __forceinline__ void unpackf2(unsigned long long v, float& lo, float& hi) {
    asm("mov.b64 {%0, %1}, %2;" : "=f"(lo), "=f"(hi) : "l"(v));
}
__device__ __forceinline__ void fma2(unsigned long long& acc,
                                     unsigned long long a, unsigned long long b) {
    asm("fma.rn.f32x2 %0, %1, %2, %0;" : "+l"(acc) : "l"(a), "l"(b));
}

__device__ __forceinline__ unsigned int tanh_h2(float lo, float hi) {
    __half2 h = __floats2half2_rn(lo, hi);
    unsigned int u;
    { union { __half2 h; unsigned int u; } cvt; cvt.h = h; u = cvt.u; }
    asm("tanh.approx.f16x2 %0, %0;" : "+r"(u));
    return u;
}

__device__ __forceinline__ uint4 pack_row(const float* v) {
    float mx = fabsf(v[0]);
#pragma unroll
    for (int o = 1; o < 9; o++) mx = fmaxf(mx, fabsf(v[o]));
    // quantize against the STORED (fp16-rounded) scale: no systematic scale error
    __half hs = __float2half_rn(fmaxf(mx, 1e-20f) * (1.0f / 2047.0f));
    float inv = __fdividef(1.0f, __half2float(hs));

    unsigned int q[9];
#pragma unroll
    for (int o = 0; o < 9; o++) {
        int qi = __float2int_rn(v[o] * inv);
        qi = max(-2047, min(2047, qi));
        q[o] = (unsigned int)(qi + 2048);
    }
    uint4 w;
    w.x = q[0] | (q[1] << 12) | (q[2] << 24);
    w.y = (q[2] >> 8) | (q[3] << 4) | (q[4] << 16) | (q[5] << 28);
    w.z = (q[5] >> 4) | (q[6] << 8) | (q[7] << 20);
    w.w = q[8] | ((unsigned int)__half_as_ushort(hs) << 16);
    return w;
}

__device__ __forceinline__ void unpack_row(uint4 w, float q[9], float& s) {
    q[0] = (float)( w.x        & 0xFFFu);
    q[1] = (float)((w.x >> 12) & 0xFFFu);
    q[2] = (float)(((w.x >> 24) | (w.y << 8)) & 0xFFFu);
    q[3] = (float)((w.y >> 4)  & 0xFFFu);
    q[4] = (float)((w.y >> 16) & 0xFFFu);
    q[5] = (float)(((w.y >> 28) | (w.z << 4)) & 0xFFFu);
    q[6] = (float)((w.z >> 8)  & 0xFFFu);
    q[7] = (float)( w.z >> 20);
    q[8] = (float)( w.w        & 0xFFFu);
    s = __half2float(__ushort_as_half((unsigned short)(w.w >> 16)));
}

__device__ __forceinline__ void decode_edge_sum(uint4 yw, uint4 zw, float* a) {
    float qy[9], qz[9], sy, sz;
    unpack_row(yw, qy, sy);
    unpack_row(zw, qz, sz);
    float c = -2048.0f * (sy + sz);
#pragma unroll
    for (int o = 0; o < 9; o++)
        a[o] = fmaf(sy, qy[o], fmaf(sz, qz[o], c));
}

// ---------------------------------------------------------------------------
// Kernel 1: per-node precompute with packed f32x2 FMAs (288 instr/node).
// PDL trigger at block start. (R15, unchanged.)
// ---------------------------------------------------------------------------
__global__ void __launch_bounds__(256)
node_precompute(const float* __restrict__ x,
                const int* __restrict__ node_types,
                const float* __restrict__ W,
                int N) {
    asm volatile("griddepcontrol.launch_dependents;" ::: "memory");

    // sWp[o*36+d]    = (W[o][d], W[o][32+d])        d in [0,32)
    // sWp[o*36+32+t] = (W[o][64+t], W[o][68+t])     t in [0,4)
    __shared__ __align__(16) float2 sWp[9 * 36];
    __shared__ __align__(16) float xs[256 * 36];

    for (int i = threadIdx.x; i < 9 * 36; i += 256) {
        int o = i / 36, d = i % 36;
        float a, b;
        if (d < 32) { a = W[o * 72 + d];             b = W[o * 72 + 32 + d]; }
        else        { a = W[o * 72 + 64 + (d - 32)]; b = W[o * 72 + 68 + (d - 32)]; }
        sWp[i] = make_float2(a, b);
    }

    int base = blockIdx.x * 256;
    const float4* xp = reinterpret_cast<const float4*>(x);
#pragma unroll
    for (int i = 0; i < 8; i++) {
        int lin = i * 256 + threadIdx.x;
        int nl  = lin >> 3;
        int cp  = lin & 7;
        if (base + nl < N)
            *reinterpret_cast<float4*>(xs + nl * 36 + cp * 4) =
                xp[(size_t)(base + nl) * 8 + cp];
    }
    __syncthreads();

    int n = base + threadIdx.x;
    if (n >= N) return;

    int t = node_types[n];

    unsigned long long acc[9];
#pragma unroll
    for (int o = 0; o < 9; o++)
        acc[o] = *reinterpret_cast<const unsigned long long*>(&sWp[o * 36 + 32 + t]);

    const float4* xrow = reinterpret_cast<const float4*>(xs + threadIdx.x * 36);
#pragma unroll
    for (int i = 0; i < 8; i++) {
        float4 xv = xrow[i];
        unsigned long long x0 = packf2(xv.x, xv.x);
        unsigned long long x1 = packf2(xv.y, xv.y);
        unsigned long long x2 = packf2(xv.z, xv.z);
        unsigned long long x3 = packf2(xv.w, xv.w);
#pragma unroll
        for (int o = 0; o < 9; o++) {
            const ulonglong2* wp =
                reinterpret_cast<const ulonglong2*>(&sWp[o * 36 + 4 * i]);
            ulonglong2 wa = wp[0];   // pairs for d=4i, 4i+1
            ulonglong2 wb = wp[1];   // pairs for d=4i+2, 4i+3
            fma2(acc[o], x0, wa.x);
            fma2(acc[o], x1, wa.y);
            fma2(acc[o], x2, wb.x);
            fma2(acc[o], x3, wb.y);
        }
    }

    float yv[9], zv[9];
#pragma unroll
    for (int o = 0; o < 9; o++) unpackf2(acc[o], yv[o], zv[o]);
    g_Y[n] = pack_row(yv);
    g_Z[n] = pack_row(zv);
}

// ---------------------------------------------------------------------------
// Kernel 2 (R7 body + PDL + float4 output): ei loads BEFORE griddepcontrol.wait;
// 2 edges/thread; 4 scattered LDG.128; SIMD tanh; half2 staging; the read-out
// loop now converts half2 pairs -> float4 and stores with STG.128 (half the
// store instructions / issue cycles of the STG.64 version).
// ---------------------------------------------------------------------------
__global__ void __launch_bounds__(256)
edge_kernel(const int* __restrict__ ei,
            float* __restrict__ out,
            int E) {
    __shared__ unsigned int sbuf[EPB * 9 / 2];   // 2304 half2 = 9216 B

    int t  = blockIdx.x * 256 + threadIdx.x;   // pair index
    int e0 = 2 * t;
    bool v0 = (e0 < E), v1 = (e0 + 1 < E);

    // ---- prologue: table-independent index loads ----
    int2 sp = make_int2(0, 0), dp = make_int2(0, 0);
    if (v1) {
        if ((E & 1) == 0) {
            sp = reinterpret_cast<const int2*>(ei)[t];
            dp = reinterpret_cast<const int2*>(ei + E)[t];
        } else {
            sp = make_int2(ei[e0], ei[e0 + 1]);
            dp = make_int2(ei[E + e0], ei[E + e0 + 1]);
        }
    } else if (v0) {
        sp.x = ei[e0];
        dp.x = ei[E + e0];
    }

    // ---- wait for the precompute grid's memory to be visible ----
    asm volatile("griddepcontrol.wait;" ::: "memory");

    uint4 y0, y1, z0, z1;
    if (v1) {
        y0 = __ldg(&g_Y[sp.x]);
        z0 = __ldg(&g_Z[dp.x]);
        y1 = __ldg(&g_Y[sp.y]);
        z1 = __ldg(&g_Z[dp.y]);
    } else if (v0) {
        y0 = __ldg(&g_Y[sp.x]);
        z0 = __ldg(&g_Z[dp.x]);
        y1 = make_uint4(0, 0, 0, 0);
        z1 = make_uint4(0, 0, 0, 0);
    } else {
        y0 = y1 = z0 = z1 = make_uint4(0, 0, 0, 0);
    }

    float a[18];
    decode_edge_sum(y0, z0, a);
    decode_edge_sum(y1, z1, a + 9);

#pragma unroll
    for (int k = 0; k < 9; k++)
        sbuf[threadIdx.x * 9 + k] = tanh_h2(a[2 * k], a[2 * k + 1]);
    __syncthreads();

    // coalesced output: 1152 float4 per block (4.5 iterations of 256 threads)
    long long lim    = (long long)E * 9;              // total floats
    long long g4base = (long long)blockIdx.x * 1152;  // float4 index base
    long long lim4   = lim >> 2;                      // full float4 count
    const uint2* sb2 = reinterpret_cast<const uint2*>(sbuf);
    float4* out4 = reinterpret_cast<float4*>(out);
#pragma unroll
    for (int it = 0; it < 5; it++) {
        int i = it * 256 + threadIdx.x;               // 0..1279 (last iter half)
        if (i < 1152) {
            long long g4 = g4base + i;
            if (g4 < lim4) {
                uint2 hp = sb2[i];
                union { unsigned int u; __half2 h; } c0, c1;
                c0.u = hp.x; c1.u = hp.y;
                float2 f0 = __half22float2(c0.h);
                float2 f1 = __half22float2(c1.h);
                out4[g4] = make_float4(f0.x, f0.y, f1.x, f1.y);
            }
        }
    }
    // scalar tail (lim not divisible by 4): at most 3 floats, last block only
    long long tstart = lim4 << 2;
    long long fbase  = (long long)blockIdx.x * 4608;
    if (threadIdx.x < 4) {
        long long g = tstart + threadIdx.x;
        if (g < lim && g >= fbase && g < fbase + 4608) {
            int li = (int)(g - fbase);                // float index in block
            union { unsigned int u; __half2 h; } cvt; cvt.u = sbuf[li >> 1];
            out[g] = (li & 1) ? __high2float(cvt.h) : __low2float(cvt.h);
        }
    }
}

extern "C" void kernel_launch(void* const* d_in, const int* in_sizes, int n_in,
                              void* d_out, int out_size) {
    // metadata order: x [N,32] f32, edge_index [2,E] i32, node_types [N] i32, W [9,72] f32
    const float* x  = (const float*)d_in[0];
    const int*   ei = (const int*)d_in[1];
    const int*   nt = (const int*)d_in[2];
    const float* W  = (const float*)d_in[3];
    float* out = (float*)d_out;

    int N = in_sizes[2];
    int E = in_sizes[1] / 2;

    node_precompute<<<(N + 255) / 256, 256>>>(x, nt, W, N);

    // Edge kernel launched as a programmatic dependent of the precompute.
    cudaLaunchConfig_t cfg = {};
    cfg.gridDim  = dim3((E + EPB - 1) / EPB, 1, 1);
    cfg.blockDim = dim3(256, 1, 1);
    cfg.dynamicSmemBytes = 0;
    cudaLaunchAttribute attrs[1];
    attrs[0].id = cudaLaunchAttributeProgrammaticStreamSerialization;
    attrs[0].val.programmaticStreamSerializationAllowed = 1;
    cfg.attrs = attrs;
    cfg.numAttrs = 1;
    cudaLaunchKernelEx(&cfg, edge_kernel, ei, out, E);
}

// round 17
// speedup vs baseline: 1.0082x; 1.0082x over previous
#include <cuda_runtime.h>
#include <cuda_fp16.h>
#include <cstdint>

#define MAXN 131072
#define EPB 512   // edges per block (256 threads x 2)

// Packed tables: one uint4 (16B) per node per table.
// 12-bit unsigned q values (bias 2048) + fp16 row scale.
__device__ uint4 g_Y[MAXN];
__device__ uint4 g_Z[MAXN];

// ---------------- helpers ----------------
__device__ __forceinline__ unsigned long long packf2(float lo, float hi) {
    unsigned long long r;
    asm("mov.b64 %0, {%1, %2};" : "=l"(r) : "f"(lo), "f"(hi));
    return r;
}
__device__ __forceinline__ void unpackf2(unsigned long long v, float& lo, float& hi) {
    asm("mov.b64 {%0, %1}, %2;" : "=f"(lo), "=f"(hi) : "l"(v));
}
__device__ __forceinline__ void fma2(unsigned long long& acc,
                                     unsigned long long a, unsigned long long b) {
    asm("fma.rn.f32x2 %0, %1, %2, %0;" : "+l"(acc) : "l"(a), "l"(b));
}

__device__ __forceinline__ unsigned int tanh_h2(float lo, float hi) {
    __half2 h = __floats2half2_rn(lo, hi);
    unsigned int u;
    { union { __half2 h; unsigned int u; } cvt; cvt.h = h; u = cvt.u; }
    asm("tanh.approx.f16x2 %0, %0;" : "+r"(u));
    return u;
}

// streaming (evict-first) 8B store: keep the output stream from evicting the
// Y/Z tables out of L2
__device__ __forceinline__ void stg_cs_f2(float2* p, float2 v) {
    asm volatile("st.global.cs.v2.f32 [%0], {%1, %2};"
                 :: "l"(p), "f"(v.x), "f"(v.y) : "memory");
}
__device__ __forceinline__ void stg_cs_f(float* p, float v) {
    asm volatile("st.global.cs.f32 [%0], %1;" :: "l"(p), "f"(v) : "memory");
}

__device__ __forceinline__ uint4 pack_row(const float* v) {
    float mx = fabsf(v[0]);
#pragma unroll
    for (int o = 1; o < 9; o++) mx = fmaxf(mx, fabsf(v[o]));
    // quantize against the STORED (fp16-rounded) scale: no systematic scale error
    __half hs = __float2half_rn(fmaxf(mx, 1e-20f) * (1.0f / 2047.0f));
    float inv = __fdividef(1.0f, __half2float(hs));

    unsigned int q[9];
#pragma unroll
    for (int o = 0; o < 9; o++) {
        int qi = __float2int_rn(v[o] * inv);
        qi = max(-2047, min(2047, qi));
        q[o] = (unsigned int)(qi + 2048);
    }
    uint4 w;
    w.x = q[0] | (q[1] << 12) | (q[2] << 24);
    w.y = (q[2] >> 8) | (q[3] << 4) | (q[4] << 16) | (q[5] << 28);
    w.z = (q[5] >> 4) | (q[6] << 8) | (q[7] << 20);
    w.w = q[8] | ((unsigned int)__half_as_ushort(hs) << 16);
    return w;
}

__device__ __forceinline__ void unpack_row(uint4 w, float q[9], float& s) {
    q[0] = (float)( w.x        & 0xFFFu);
    q[1] = (float)((w.x >> 12) & 0xFFFu);
    q[2] = (float)(((w.x >> 24) | (w.y << 8)) & 0xFFFu);
    q[3] = (float)((w.y >> 4)  & 0xFFFu);
    q[4] = (float)((w.y >> 16) & 0xFFFu);
    q[5] = (float)(((w.y >> 28) | (w.z << 4)) & 0xFFFu);
    q[6] = (float)((w.z >> 8)  & 0xFFFu);
    q[7] = (float)( w.z >> 20);
    q[8] = (float)( w.w        & 0xFFFu);
    s = __half2float(__ushort_as_half((unsigned short)(w.w >> 16)));
}

__device__ __forceinline__ void decode_edge_sum(uint4 yw, uint4 zw, float* a) {
    float qy[9], qz[9], sy, sz;
    unpack_row(yw, qy, sy);
    unpack_row(zw, qz, sz);
    float c = -2048.0f * (sy + sz);
#pragma unroll
    for (int o = 0; o < 9; o++)
        a[o] = fmaf(sy, qy[o], fmaf(sz, qz[o], c));
}

// ---------------------------------------------------------------------------
// Kernel 1: per-node precompute with packed f32x2 FMAs (288 instr/node).
// PDL trigger at block start. (R15, unchanged.)
// ---------------------------------------------------------------------------
__global__ void __launch_bounds__(256)
node_precompute(const float* __restrict__ x,
                const int* __restrict__ node_types,
                const float* __restrict__ W,
                int N) {
    asm volatile("griddepcontrol.launch_dependents;" ::: "memory");

    // sWp[o*36+d]    = (W[o][d], W[o][32+d])        d in [0,32)
    // sWp[o*36+32+t] = (W[o][64+t], W[o][68+t])     t in [0,4)
    __shared__ __align__(16) float2 sWp[9 * 36];
    __shared__ __align__(16) float xs[256 * 36];

    for (int i = threadIdx.x; i < 9 * 36; i += 256) {
        int o = i / 36, d = i % 36;
        float a, b;
        if (d < 32) { a = W[o * 72 + d];             b = W[o * 72 + 32 + d]; }
        else        { a = W[o * 72 + 64 + (d - 32)]; b = W[o * 72 + 68 + (d - 32)]; }
        sWp[i] = make_float2(a, b);
    }

    int base = blockIdx.x * 256;
    const float4* xp = reinterpret_cast<const float4*>(x);
#pragma unroll
    for (int i = 0; i < 8; i++) {
        int lin = i * 256 + threadIdx.x;
        int nl  = lin >> 3;
        int cp  = lin & 7;
        if (base + nl < N)
            *reinterpret_cast<float4*>(xs + nl * 36 + cp * 4) =
                xp[(size_t)(base + nl) * 8 + cp];
    }
    __syncthreads();

    int n = base + threadIdx.x;
    if (n >= N) return;

    int t = node_types[n];

    unsigned long long acc[9];
#pragma unroll
    for (int o = 0; o < 9; o++)
        acc[o] = *reinterpret_cast<const unsigned long long*>(&sWp[o * 36 + 32 + t]);

    const float4* xrow = reinterpret_cast<const float4*>(xs + threadIdx.x * 36);
#pragma unroll
    for (int i = 0; i < 8; i++) {
        float4 xv = xrow[i];
        unsigned long long x0 = packf2(xv.x, xv.x);
        unsigned long long x1 = packf2(xv.y, xv.y);
        unsigned long long x2 = packf2(xv.z, xv.z);
        unsigned long long x3 = packf2(xv.w, xv.w);
#pragma unroll
        for (int o = 0; o < 9; o++) {
            const ulonglong2* wp =
                reinterpret_cast<const ulonglong2*>(&sWp[o * 36 + 4 * i]);
            ulonglong2 wa = wp[0];   // pairs for d=4i, 4i+1
            ulonglong2 wb = wp[1];   // pairs for d=4i+2, 4i+3
            fma2(acc[o], x0, wa.x);
            fma2(acc[o], x1, wa.y);
            fma2(acc[o], x2, wb.x);
            fma2(acc[o], x3, wb.y);
        }
    }

    float yv[9], zv[9];
#pragma unroll
    for (int o = 0; o < 9; o++) unpackf2(acc[o], yv[o], zv[o]);
    g_Y[n] = pack_row(yv);
    g_Z[n] = pack_row(zv);
}

// ---------------------------------------------------------------------------
// Kernel 2 (R15 body + streaming output stores): ei loads BEFORE
// griddepcontrol.wait; 2 edges/thread; 4 scattered LDG.128; SIMD tanh;
// half2 staging; coalesced st.global.cs.v2.f32 output (evict-first so the
// 57.6MB write stream doesn't evict the 3.2MB Y/Z tables from L2).
// ---------------------------------------------------------------------------
__global__ void __launch_bounds__(256)
edge_kernel(const int* __restrict__ ei,
            float* __restrict__ out,
            int E) {
    __shared__ unsigned int sbuf[EPB * 9 / 2];   // 2304 half2 = 9216 B

    int t  = blockIdx.x * 256 + threadIdx.x;   // pair index
    int e0 = 2 * t;
    bool v0 = (e0 < E), v1 = (e0 + 1 < E);

    // ---- prologue: table-independent index loads ----
    int2 sp = make_int2(0, 0), dp = make_int2(0, 0);
    if (v1) {
        if ((E & 1) == 0) {
            sp = reinterpret_cast<const int2*>(ei)[t];
            dp = reinterpret_cast<const int2*>(ei + E)[t];
        } else {
            sp = make_int2(ei[e0], ei[e0 + 1]);
            dp = make_int2(ei[E + e0], ei[E + e0 + 1]);
        }
    } else if (v0) {
        sp.x = ei[e0];
        dp.x = ei[E + e0];
    }

    // ---- wait for the precompute grid's memory to be visible ----
    asm volatile("griddepcontrol.wait;" ::: "memory");

    uint4 y0, y1, z0, z1;
    if (v1) {
        y0 = __ldg(&g_Y[sp.x]);
        z0 = __ldg(&g_Z[dp.x]);
        y1 = __ldg(&g_Y[sp.y]);
        z1 = __ldg(&g_Z[dp.y]);
    } else if (v0) {
        y0 = __ldg(&g_Y[sp.x]);
        z0 = __ldg(&g_Z[dp.x]);
        y1 = make_uint4(0, 0, 0, 0);
        z1 = make_uint4(0, 0, 0, 0);
    } else {
        y0 = y1 = z0 = z1 = make_uint4(0, 0, 0, 0);
    }

    float a[18];
    decode_edge_sum(y0, z0, a);
    decode_edge_sum(y1, z1, a + 9);

#pragma unroll
    for (int k = 0; k < 9; k++)
        sbuf[threadIdx.x * 9 + k] = tanh_h2(a[2 * k], a[2 * k + 1]);
    __syncthreads();

    // coalesced output: 2304 half2 per block -> streaming float2 stores
    long long lim    = (long long)E * 9;               // total floats
    long long g2base = (long long)blockIdx.x * 2304;   // half2 index base
    float2* out2 = reinterpret_cast<float2*>(out);
#pragma unroll
    for (int it = 0; it < 9; it++) {
        int i = it * 256 + threadIdx.x;                // 0..2303
        long long g2 = g2base + i;
        long long f0 = 2 * g2;
        if (f0 + 1 < lim) {
            union { unsigned int u; __half2 h; } cvt; cvt.u = sbuf[i];
            stg_cs_f2(&out2[g2], __half22float2(cvt.h));
        } else if (f0 < lim) {
            union { unsigned int u; __half2 h; } cvt; cvt.u = sbuf[i];
            stg_cs_f(&out[f0], __low2float(cvt.h));
        }
    }
}

extern "C" void kernel_launch(void* const* d_in, const int* in_sizes, int n_in,
                              void* d_out, int out_size) {
    // metadata order: x [N,32] f32, edge_index [2,E] i32, node_types [N] i32, W [9,72] f32
    const float* x  = (const float*)d_in[0];
    const int*   ei = (const int*)d_in[1];
    const int*   nt = (const int*)d_in[2];
    const float* W  = (const float*)d_in[3];
    float* out = (float*)d_out;

    int N = in_sizes[2];
    int E = in_sizes[1] / 2;

    node_precompute<<<(N + 255) / 256, 256>>>(x, nt, W, N);

    // Edge kernel launched as a programmatic dependent of the precompute.
    cudaLaunchConfig_t cfg = {};
    cfg.gridDim  = dim3((E + EPB - 1) / EPB, 1, 1);
    cfg.blockDim = dim3(256, 1, 1);
    cfg.dynamicSmemBytes = 0;
    cudaLaunchAttribute attrs[1];
    attrs[0].id = cudaLaunchAttributeProgrammaticStreamSerialization;
    attrs[0].val.programmaticStreamSerializationAllowed = 1;
    cfg.attrs = attrs;
    cfg.numAttrs = 1;
    cudaLaunchKernelEx(&cfg, edge_kernel, ei, out, E);
}